// round 15
// baseline (speedup 1.0000x reference)
#include <cuda_runtime.h>
#include <cuda_bf16.h>
#include <cstdint>

#define NB   8            // b's per tile
#define TPB  128          // 16 threads per b, 4 candidates per thread
#define EPS  1e-6f
typedef unsigned long long ull;

#define RP_F     (NB * 576)            // 4608 floats R_pred per stage
#define GT_F     (NB * 9)              // 72 floats R_gt per stage
#define STAGE_F  (RP_F + GT_F)         // 4680 floats = 18720 B (16B multiple)
#define SMEM_BYTES (2 * STAGE_F * 4)   // 37440 B dynamic

__device__ float g_partial[1024];
__device__ unsigned int g_count = 0;    // self-resets via atomicInc wrap

__global__ __launch_bounds__(TPB, 6)
void geo_tma(const float* __restrict__ R_pred,
             const float* __restrict__ R_gt,
             const float* __restrict__ rot,
             float* __restrict__ out,
             int B, int ntiles, int grid, float invB)
{
    extern __shared__ float sm[];           // 2 x STAGE_F buffers (16B aligned)
    __shared__ alignas(8) ull mbar[2];
    __shared__ float gdup[240];             // rot duplicated pairs, warp-uniform
    __shared__ float ssum;
    __shared__ int slast;

    const int tid = threadIdx.x;
    const int bl  = tid >> 4;               // local b within tile
    const int m   = tid & 15;               // candidate group (4 candidates)

    const uint32_t mb0 = (uint32_t)__cvta_generic_to_shared(&mbar[0]);
    const uint32_t mb1 = (uint32_t)__cvta_generic_to_shared(&mbar[1]);
    const uint32_t sm0 = (uint32_t)__cvta_generic_to_shared(sm);

    if (tid < 108) {
        const int s = tid / 9, e = tid - s * 9;
        float v = __ldg(rot + tid);
        gdup[s * 20 + e * 2]     = v;
        gdup[s * 20 + e * 2 + 1] = v;
    }
    if (tid == 0) {
        ssum = 0.0f;
        asm volatile("mbarrier.init.shared.b64 [%0], 1;" :: "r"(mb0));
        asm volatile("mbarrier.init.shared.b64 [%0], 1;" :: "r"(mb1));
    }
    __syncthreads();

    // stage tile t into buffer p: R_pred bulk + R_gt bulk, one mbarrier (tid==0)
    auto stage = [&](int t, int p) {
        const int nb = min(NB, B - t * NB);
        const uint32_t bytes1 = (uint32_t)nb * 2304u;
        const uint32_t bytes2 = (uint32_t)nb * 36u;
        const bool gt_bulk = (bytes2 & 15u) == 0u;   // 16B-aligned size
        const uint32_t mb = p ? mb1 : mb0;
        const uint32_t base = sm0 + (uint32_t)p * (STAGE_F * 4u);
        asm volatile("mbarrier.arrive.expect_tx.shared.b64 _, [%0], %1;"
                     :: "r"(mb), "r"(bytes1 + (gt_bulk ? bytes2 : 0u)));
        asm volatile("cp.async.bulk.shared::cta.global.mbarrier::complete_tx::bytes "
                     "[%0], [%1], %2, [%3];"
                     :: "r"(base), "l"(R_pred + (size_t)t * NB * 576), "r"(bytes1), "r"(mb)
                     : "memory");
        if (gt_bulk)
            asm volatile("cp.async.bulk.shared::cta.global.mbarrier::complete_tx::bytes "
                         "[%0], [%1], %2, [%3];"
                         :: "r"(base + RP_F * 4u), "l"(R_gt + (size_t)t * NB * 9),
                            "r"(bytes2), "r"(mb)
                         : "memory");
    };

    if (tid == 0) {
        stage(blockIdx.x, 0);
        if (blockIdx.x + grid < ntiles) stage(blockIdx.x + grid, 1);
    }

    int ph0 = 0, ph1 = 0;
    int p = 0;
    for (int t = blockIdx.x; t < ntiles; t += grid, p ^= 1) {
        // wait for buffer p (parity)
        {
            const uint32_t mb = p ? mb1 : mb0;
            const uint32_t phase = (uint32_t)(p ? ph1 : ph0);
            uint32_t done;
            do {
                asm volatile(
                    "{\n\t.reg .pred P;\n\t"
                    "mbarrier.try_wait.parity.acquire.cta.shared::cta.b64 P, [%1], %2, 0x989680;\n\t"
                    "selp.b32 %0, 1, 0, P;\n\t}"
                    : "=r"(done) : "r"(mb), "r"(phase) : "memory");
            } while (!done);
            if (p) ph1 ^= 1; else ph0 ^= 1;
        }

        const int nb = min(NB, B - t * NB);
        const bool gt_in_smem = ((nb * 36) & 15) == 0;
        const float* S = sm + p * STAGE_F;
        float cmax = -1e30f;

        if (bl < nb) {
            // R_gt[b]: LDS broadcast from staged buffer (29 cyc, not 250)
            float g[9];
            if (gt_in_smem) {
                const float* gp = S + RP_F + bl * 9;
                #pragma unroll
                for (int k = 0; k < 9; k++) g[k] = gp[k];
            } else {
                const float* gp = R_gt + (size_t)(t * NB + bl) * 9;
                #pragma unroll
                for (int k = 0; k < 9; k++) g[k] = __ldg(gp + k);
            }

            // 4 candidates = 9 conflict-free LDS.128
            float rp[36];
            const float4* p4 = reinterpret_cast<const float4*>(&S[(bl * 64 + m * 4) * 9]);
            #pragma unroll
            for (int k = 0; k < 9; k++) {
                float4 v = p4[k];
                rp[4*k+0] = v.x; rp[4*k+1] = v.y; rp[4*k+2] = v.z; rp[4*k+3] = v.w;
            }

            // M[c][i*3+k] = sum_j rp[c,i,j]*g[k*3+j]; pack candidate pairs
            ull a[9], bq[9];
            #pragma unroll
            for (int e = 0; e < 9; e++) {
                const int i3 = (e / 3) * 3, k3 = (e % 3) * 3;
                float m0 = fmaf(rp[ 0+i3+2], g[k3+2], fmaf(rp[ 0+i3+1], g[k3+1], rp[ 0+i3] * g[k3]));
                float m1 = fmaf(rp[ 9+i3+2], g[k3+2], fmaf(rp[ 9+i3+1], g[k3+1], rp[ 9+i3] * g[k3]));
                float m2 = fmaf(rp[18+i3+2], g[k3+2], fmaf(rp[18+i3+1], g[k3+1], rp[18+i3] * g[k3]));
                float m3 = fmaf(rp[27+i3+2], g[k3+2], fmaf(rp[27+i3+1], g[k3+1], rp[27+i3] * g[k3]));
                asm("mov.b64 %0, {%1, %2};" : "=l"(a[e])  : "f"(m0), "f"(m1));
                asm("mov.b64 %0, {%1, %2};" : "=l"(bq[e]) : "f"(m2), "f"(m3));
            }

            // s-loop: tr[c,s] = <rot[s], M[c]> via duplicated-pair f32x2
            #pragma unroll
            for (int s = 0; s < 12; s++) {
                const ull* gq = reinterpret_cast<const ull*>(gdup + s * 20);
                ull acc0 = 0ull, acc1 = 0ull;
                #pragma unroll
                for (int h = 0; h < 4; h++) {          // broadcast LDS.128
                    ulonglong2 q = reinterpret_cast<const ulonglong2*>(gq)[h];
                    asm("fma.rn.f32x2 %0, %1, %2, %3;" : "=l"(acc0) : "l"(a[2*h]),    "l"(q.x), "l"(acc0));
                    asm("fma.rn.f32x2 %0, %1, %2, %3;" : "=l"(acc1) : "l"(bq[2*h]),   "l"(q.x), "l"(acc1));
                    asm("fma.rn.f32x2 %0, %1, %2, %3;" : "=l"(acc0) : "l"(a[2*h+1]),  "l"(q.y), "l"(acc0));
                    asm("fma.rn.f32x2 %0, %1, %2, %3;" : "=l"(acc1) : "l"(bq[2*h+1]), "l"(q.y), "l"(acc1));
                }
                ull g8 = gq[8];
                asm("fma.rn.f32x2 %0, %1, %2, %3;" : "=l"(acc0) : "l"(a[8]),  "l"(g8), "l"(acc0));
                asm("fma.rn.f32x2 %0, %1, %2, %3;" : "=l"(acc1) : "l"(bq[8]), "l"(g8), "l"(acc1));

                float2 f0 = *reinterpret_cast<float2*>(&acc0);
                float2 f1 = *reinterpret_cast<float2*>(&acc1);
                cmax = fmaxf(cmax, fmaxf(fmaxf(f0.x, f0.y), fmaxf(f1.x, f1.y)));
            }
        }

        // max over the 16 lanes sharing this b
        #pragma unroll
        for (int w = 8; w >= 1; w >>= 1)
            cmax = fmaxf(cmax, __shfl_xor_sync(0xFFFFFFFFu, cmax, w));

        if (m == 0 && bl < nb) {
            float cosv = (cmax - 1.0f) * 0.5f;
            cosv = fminf(fmaxf(cosv, -1.0f + EPS), 1.0f - EPS);
            atomicAdd(&ssum, acosf(cosv));
        }
        __syncthreads();           // all threads done reading buffer p

        // restage buffer p with tile t + 2*grid
        const int t2 = t + 2 * grid;
        if (tid == 0 && t2 < ntiles) stage(t2, p);
    }

    // ---- publish per-CTA sum; last CTA reduces (counter wraps to 0) ----
    if (tid == 0) {
        g_partial[blockIdx.x] = ssum;
        __threadfence();
        unsigned int old = atomicInc(&g_count, (unsigned int)(grid - 1));
        slast = (old == (unsigned int)(grid - 1));
    }
    __syncthreads();

    if (slast) {
        __shared__ float warpsum[TPB / 32];
        float v = 0.0f;
        for (int i = tid; i < grid; i += TPB) v += __ldcg(&g_partial[i]);
        #pragma unroll
        for (int w = 16; w >= 1; w >>= 1)
            v += __shfl_xor_sync(0xFFFFFFFFu, v, w);
        if ((tid & 31) == 0) warpsum[tid >> 5] = v;
        __syncthreads();
        if (tid < TPB / 32) {
            float w2 = warpsum[tid];
            #pragma unroll
            for (int w = TPB / 64; w >= 1; w >>= 1)
                w2 += __shfl_xor_sync(0xFFu, w2, w);
            if (tid == 0) out[0] = w2 * invB;
        }
    }
}

extern "C" void kernel_launch(void* const* d_in, const int* in_sizes, int n_in,
                              void* d_out, int out_size)
{
    const float* R_pred = (const float*)d_in[0];
    const float* R_gt   = (const float*)d_in[1];
    const float* rot    = (const float*)d_in[2];
    float* out = (float*)d_out;

    const int B = in_sizes[1] / 9;
    const int ntiles = (B + NB - 1) / NB;
    int grid = 6 * 148;                       // 6 CTAs/SM persistent
    if (grid > ntiles) grid = ntiles;

    cudaFuncSetAttribute(geo_tma, cudaFuncAttributeMaxDynamicSharedMemorySize, SMEM_BYTES);
    geo_tma<<<grid, TPB, SMEM_BYTES>>>(R_pred, R_gt, rot, out,
                                       B, ntiles, grid, 1.0f / (float)B);
}